// round 6
// baseline (speedup 1.0000x reference)
#include <cuda_runtime.h>
#include <math.h>

#define B_    2
#define CIN   32
#define COUT  32
#define D_    40
#define E_    3
#define SP    (D_*D_*D_)          // 64000
#define YTOT  (B_*COUT*SP)        // 4,096,000
#define TZ    2
#define NZT   (D_/TZ)             // 20
#define SLABZ (TZ+2)              // 4
#define SROW  48                  // padded row stride (floats), 192B (16B-mult)
#define NROWS (SLABZ*42)          // 168 rows per slab
#define SLABVOL (NROWS*SROW)      // 8064 floats
#define WPB   (CIN*27)            // 864

// ---- scratch (device globals; no runtime allocation) ----
__device__ float g_w[B_*COUT*WPB];
__device__ float g_bias[B_*COUT];
__device__ float g_y[YTOT];             // pre-upsample activations (16.4 MB)
__device__ float g_sum[COUT];
__device__ float g_sumsq[COUT];
__device__ float g_scale[COUT];
__device__ float g_shift[COUT];

// ---------------------------------------------------------------------------
// Kernel 1: routing + combined weights/bias, zero stat accumulators
// ---------------------------------------------------------------------------
__global__ void k_route(const float* __restrict__ emb,
                        const float* __restrict__ rw,
                        const float* __restrict__ rb,
                        const float* __restrict__ ek,
                        const float* __restrict__ eb) {
    float r[B_][E_];
    #pragma unroll
    for (int b = 0; b < B_; b++)
        #pragma unroll
        for (int e = 0; e < E_; e++) {
            float t = fmaf(emb[b], rw[e], rb[e]);
            r[b][e] = 1.0f / (1.0f + expf(-t));
        }

    int idx = blockIdx.x * blockDim.x + threadIdx.x;
    const int W = COUT * CIN * 27;
    if (idx < B_ * W) {
        int b = idx / W;
        int w = idx - b * W;
        float s = 0.0f;
        #pragma unroll
        for (int e = 0; e < E_; e++) s = fmaf(r[b][e], ek[e * W + w], s);
        g_w[idx] = s;
    }
    if (idx < B_ * COUT) {
        int b = idx / COUT, o = idx - b * COUT;
        float s = 0.0f;
        #pragma unroll
        for (int e = 0; e < E_; e++) s = fmaf(r[b][e], eb[e * COUT + o], s);
        g_bias[idx] = s;
    }
    if (idx < COUT) { g_sum[idx] = 0.0f; g_sumsq[idx] = 0.0f; }
}

// ---------------------------------------------------------------------------
// Kernel 2: direct 3x3x3 conv + bias + BN stats.
//   - 16B cp.async double-buffered slab; halo pre-zeroed once (never rewritten)
//   - scalar acc[2][8]: ~60 regs, no spill under __launch_bounds__(224,2)
// grid = (20, 32, 2), block = 224 (t<200 compute, t<168 load one row each)
// ---------------------------------------------------------------------------
__global__ void __launch_bounds__(224, 2)
k_conv(const float* __restrict__ x) {
    extern __shared__ float dyn[];
    float* sh  = dyn;                    // [2][SLABVOL]
    float* wsh = dyn + 2 * SLABVOL;      // [WPB]
    float* red = wsh + WPB;              // [16]

    const int zt = blockIdx.x;            // 0..19
    const int oc = blockIdx.y;
    const int b  = blockIdx.z;
    const int t  = threadIdx.x;
    const int z0 = zt * TZ;

    // zero everything once: halo columns/rows stay zero for all ic
    for (int i = t; i < 2 * SLABVOL + WPB + 16; i += 224) dyn[i] = 0.0f;
    __syncthreads();

    // weights for this (b, oc)
    for (int i = t; i < WPB; i += 224)
        wsh[i] = g_w[(b * COUT + oc) * WPB + i];

    // ---- loader: one smem row per thread (t < 168), 10 x 16B cp.async ----
    const float* xb = x + (size_t)(b * CIN) * SP;
    const int lz = t / 42, ly = t - 42 * (t / 42);
    const int gz = z0 - 1 + lz, gy = ly - 1;
    const bool rowok = (t < NROWS) && ((unsigned)gz < D_) && ((unsigned)gy < D_);
    const long grow = (long)gz * 1600 + (long)gy * 40;
    // interior columns 4..43 within SROW=48 row; dst 16B aligned
    const unsigned sdst0 = (unsigned)__cvta_generic_to_shared(sh)
                         + (unsigned)(t * (SROW * 4) + 16);

    auto prefetch = [&](int ic, int buf) {
        if (!rowok) return;
        const float* src = xb + (size_t)ic * SP + grow;
        unsigned d = sdst0 + (unsigned)buf * (SLABVOL * 4);
        #pragma unroll
        for (int c = 0; c < 10; c++)
            asm volatile("cp.async.cg.shared.global [%0], [%1], 16;"
                         :: "r"(d + c * 16), "l"(src + c * 4));
    };

    // ---- compute setup ----
    const int ty = t / 5;                 // 0..39
    const int xs = (t % 5) * 8;           // 0,8,16,24,32
    const bool active = (t < 200);

    float acc[TZ][8];
    #pragma unroll
    for (int z = 0; z < TZ; z++)
        #pragma unroll
        for (int j = 0; j < 8; j++) acc[z][j] = 0.0f;

    prefetch(0, 0);
    asm volatile("cp.async.commit_group;");

    for (int ic = 0; ic < CIN; ic++) {
        __syncthreads();                       // prev compute done on buf^1
        if (ic + 1 < CIN) prefetch(ic + 1, (ic + 1) & 1);
        asm volatile("cp.async.commit_group;");
        asm volatile("cp.async.wait_group 1;");   // buffer (ic&1) ready
        __syncthreads();

        if (active) {
            const float* S  = sh + (ic & 1) * SLABVOL;
            const float* wv = wsh + ic * 27;
            #pragma unroll 1
            for (int ky = 0; ky < 3; ky++) {
                float w[3][3];
                #pragma unroll
                for (int dz = 0; dz < 3; dz++)
                    #pragma unroll
                    for (int kx = 0; kx < 3; kx++)
                        w[dz][kx] = wv[dz * 9 + ky * 3 + kx];
                #pragma unroll
                for (int zz = 0; zz < SLABZ; zz++) {
                    // window: input cols (xs-1 .. xs+8) => smem cols 3+xs .. 12+xs
                    const float* rowp = S + (zz * 42 + ty + ky) * SROW + 3 + xs;
                    float f[10];
                    f[0] = rowp[0];
                    float4 a = *(const float4*)(rowp + 1);   // col 4+xs: aligned
                    float4 c4 = *(const float4*)(rowp + 5);  // col 8+xs: aligned
                    f[1] = a.x; f[2] = a.y; f[3] = a.z; f[4] = a.w;
                    f[5] = c4.x; f[6] = c4.y; f[7] = c4.z; f[8] = c4.w;
                    f[9] = rowp[9];
                    #pragma unroll
                    for (int dz = 0; dz < 3; dz++) {
                        const int z = zz - dz;
                        if (z >= 0 && z < TZ) {    // compile-time after unroll
                            #pragma unroll
                            for (int kx = 0; kx < 3; kx++) {
                                float ww = w[dz][kx];
                                #pragma unroll
                                for (int j = 0; j < 8; j++)
                                    acc[z][j] = fmaf(ww, f[j + kx], acc[z][j]);
                            }
                        }
                    }
                }
            }
        }
    }

    // ---- epilogue: bias, store y, BN partial sums ----
    float s1 = 0.0f, s2 = 0.0f;
    if (active) {
        const float bias = g_bias[b * COUT + oc];
        float* yp = g_y + (size_t)(b * COUT + oc) * SP + z0 * 1600 + ty * 40 + xs;
        #pragma unroll
        for (int z = 0; z < TZ; z++) {
            float4 q0, q1; float v;
            v = acc[z][0] + bias; s1 += v; s2 = fmaf(v, v, s2); q0.x = v;
            v = acc[z][1] + bias; s1 += v; s2 = fmaf(v, v, s2); q0.y = v;
            v = acc[z][2] + bias; s1 += v; s2 = fmaf(v, v, s2); q0.z = v;
            v = acc[z][3] + bias; s1 += v; s2 = fmaf(v, v, s2); q0.w = v;
            v = acc[z][4] + bias; s1 += v; s2 = fmaf(v, v, s2); q1.x = v;
            v = acc[z][5] + bias; s1 += v; s2 = fmaf(v, v, s2); q1.y = v;
            v = acc[z][6] + bias; s1 += v; s2 = fmaf(v, v, s2); q1.z = v;
            v = acc[z][7] + bias; s1 += v; s2 = fmaf(v, v, s2); q1.w = v;
            *(float4*)(yp + z * 1600)     = q0;
            *(float4*)(yp + z * 1600 + 4) = q1;
        }
    }
    #pragma unroll
    for (int o = 16; o > 0; o >>= 1) {
        s1 += __shfl_down_sync(0xffffffff, s1, o);
        s2 += __shfl_down_sync(0xffffffff, s2, o);
    }
    const int wid = t >> 5, lane = t & 31;
    __syncthreads();
    if (lane == 0) { red[wid] = s1; red[8 + wid] = s2; }
    __syncthreads();
    if (t == 0) {
        float a = 0.0f, q = 0.0f;
        #pragma unroll
        for (int i = 0; i < 7; i++) { a += red[i]; q += red[8 + i]; }
        atomicAdd(&g_sum[oc], a);
        atomicAdd(&g_sumsq[oc], q);
    }
}

// ---------------------------------------------------------------------------
// Kernel 3: finalize BN -> per-channel scale/shift
// ---------------------------------------------------------------------------
__global__ void k_stats(const float* __restrict__ gamma,
                        const float* __restrict__ beta) {
    int c = threadIdx.x;
    if (c < COUT) {
        const float n = (float)(B_ * SP);
        float mean = g_sum[c] / n;
        float var  = g_sumsq[c] / n - mean * mean;
        float sc = gamma[c] * rsqrtf(var + 1e-5f);
        g_scale[c] = sc;
        g_shift[c] = beta[c] - mean * sc;
    }
}

// ---------------------------------------------------------------------------
// Kernel 4: affine + LeakyReLU + nearest upsample x2; float2 in, 4x float4 out
// ---------------------------------------------------------------------------
__global__ void __launch_bounds__(256)
k_up(float* __restrict__ out) {
    int idx = blockIdx.x * blockDim.x + threadIdx.x;  // over YTOT/2
    if (idx >= YTOT / 2) return;
    int i2 = idx * 2;
    int xw = i2 % 40;                 // even
    int rest = i2 / 40;
    int yw = rest % 40; rest /= 40;
    int zw = rest % 40; rest /= 40;
    int c  = rest % COUT;
    int b  = rest / COUT;

    float2 v = *(const float2*)&g_y[i2];
    float sc = g_scale[c], sf = g_shift[c];
    float a0 = fmaf(sc, v.x, sf); a0 = (a0 >= 0.0f) ? a0 : 0.1f * a0;
    float a1 = fmaf(sc, v.y, sf); a1 = (a1 >= 0.0f) ? a1 : 0.1f * a1;
    float4 p = make_float4(a0, a0, a1, a1);

    size_t base = ((size_t)(b * COUT + c) * 512000u)
                + (size_t)(2 * zw) * 6400u + (size_t)(2 * yw) * 80u + (size_t)(2 * xw);
    float4* o4 = (float4*)(out + base);
    o4[0]    = p;    // (2z,   2y  )
    o4[20]   = p;    // (2z,   2y+1)
    o4[1600] = p;    // (2z+1, 2y  )
    o4[1620] = p;    // (2z+1, 2y+1)
}

// ---------------------------------------------------------------------------
extern "C" void kernel_launch(void* const* d_in, const int* in_sizes, int n_in,
                              void* d_out, int out_size) {
    const float* x     = (const float*)d_in[0];
    const float* emb   = (const float*)d_in[1];
    const float* rw    = (const float*)d_in[2];
    const float* rb    = (const float*)d_in[3];
    const float* ek    = (const float*)d_in[4];
    const float* eb    = (const float*)d_in[5];
    const float* gamma = (const float*)d_in[6];
    const float* beta  = (const float*)d_in[7];
    float* out = (float*)d_out;

    k_route<<<(B_ * COUT * CIN * 27 + 255) / 256, 256>>>(emb, rw, rb, ek, eb);

    static int smem_set = 0;
    size_t shbytes = (size_t)(2 * SLABVOL + WPB + 16) * sizeof(float);  // ~68 KB
    if (!smem_set) {
        cudaFuncSetAttribute(k_conv, cudaFuncAttributeMaxDynamicSharedMemorySize, (int)shbytes);
        smem_set = 1;
    }
    dim3 gconv(NZT, COUT, B_);
    k_conv<<<gconv, 224, shbytes>>>(x);

    k_stats<<<1, 32>>>(gamma, beta);

    k_up<<<(YTOT / 2 + 255) / 256, 256>>>(out);
}

// round 7
// speedup vs baseline: 2.0797x; 2.0797x over previous
#include <cuda_runtime.h>
#include <math.h>

#define B_    2
#define CIN   32
#define COUT  32
#define D_    40
#define E_    3
#define SP    (D_*D_*D_)          // 64000
#define YTOT  (B_*COUT*SP)        // 4,096,000
#define OCG   4                   // output channels per block
#define NOCG  (COUT/OCG)          // 8
#define SROW  48                  // padded smem row stride (floats)
#define NROWS (3*42)              // 126 rows (3 z-planes x 42 y-rows)
#define SLABVOL (NROWS*SROW)      // 6048 floats
#define WBLK  (CIN*27*OCG)        // 3456 weights per block
#define WICS  (27*OCG)            // 108 weights per ic

// ---- scratch (device globals; no runtime allocation) ----
__device__ float g_w[B_*NOCG*WBLK];     // [b][ocg][ic][ky][dz][kx][oc4]
__device__ float g_bias[B_*COUT];
__device__ float g_y[YTOT];             // pre-upsample activations (16.4 MB)
__device__ float g_sum[COUT];
__device__ float g_sumsq[COUT];
__device__ float g_scale[COUT];
__device__ float g_shift[COUT];

// ---------------------------------------------------------------------------
// Kernel 1: routing + combined weights (blocked layout) + bias, zero stats
// ---------------------------------------------------------------------------
__global__ void k_route(const float* __restrict__ emb,
                        const float* __restrict__ rw,
                        const float* __restrict__ rb,
                        const float* __restrict__ ek,
                        const float* __restrict__ eb) {
    float r[B_][E_];
    #pragma unroll
    for (int b = 0; b < B_; b++)
        #pragma unroll
        for (int e = 0; e < E_; e++) {
            float t = fmaf(emb[b], rw[e], rb[e]);
            r[b][e] = 1.0f / (1.0f + expf(-t));
        }

    int idx = blockIdx.x * blockDim.x + threadIdx.x;
    const int TOT = B_ * NOCG * WBLK;   // 55296
    if (idx < TOT) {
        int rr = idx;
        int og = rr & 3;  rr >>= 2;
        int kx = rr % 3;  rr /= 3;
        int dz = rr % 3;  rr /= 3;
        int ky = rr % 3;  rr /= 3;
        int ic = rr % CIN; rr /= CIN;
        int ocg = rr % NOCG;
        int b   = rr / NOCG;
        int oc  = ocg * OCG + og;
        int tap = dz * 9 + ky * 3 + kx;
        float s = 0.0f;
        #pragma unroll
        for (int e = 0; e < E_; e++)
            s = fmaf(r[b][e], ek[((e * COUT + oc) * CIN + ic) * 27 + tap], s);
        g_w[idx] = s;
    }
    if (idx < B_ * COUT) {
        int b = idx / COUT, o = idx - b * COUT;
        float s = 0.0f;
        #pragma unroll
        for (int e = 0; e < E_; e++) s = fmaf(r[b][e], eb[e * COUT + o], s);
        g_bias[idx] = s;
    }
    if (idx < COUT) { g_sum[idx] = 0.0f; g_sumsq[idx] = 0.0f; }
}

// ---------------------------------------------------------------------------
// Kernel 2: direct 3x3x3 conv, 4 output channels per block + bias + BN stats.
//   Each f[10] row window feeds 4 oc (x3 kx x8 x = 96 FMA) -> LDS per FMA /4.
// grid = (40 z, 8 ocg, 2 b), block = 224 (t<200 compute, t<126 load rows)
// ---------------------------------------------------------------------------
__global__ void __launch_bounds__(224, 2)
k_conv(const float* __restrict__ x) {
    extern __shared__ float dyn[];
    float* sh  = dyn;                    // [2][SLABVOL]
    float* wsh = dyn + 2 * SLABVOL;      // [WBLK]
    float* red = wsh + WBLK;             // [64]

    const int z0  = blockIdx.x;           // output z, 0..39
    const int ocg = blockIdx.y;           // 0..7
    const int b   = blockIdx.z;           // 0..1
    const int t   = threadIdx.x;

    // zero slabs once: halo rows/cols stay zero for all ic
    for (int i = t; i < 2 * SLABVOL; i += 224) dyn[i] = 0.0f;
    // block weights: contiguous, coalesced
    const float* gw = g_w + (size_t)(b * NOCG + ocg) * WBLK;
    for (int i = t; i < WBLK; i += 224) wsh[i] = gw[i];

    // ---- loader: one smem row per thread (t < 126), 10 x 16B cp.async ----
    const float* xb = x + (size_t)(b * CIN) * SP;
    const int lz = t / 42, ly = t - 42 * (t / 42);
    const int gz = z0 - 1 + lz, gy = ly - 1;
    const bool rowok = (t < NROWS) && ((unsigned)gz < D_) && ((unsigned)gy < D_);
    const long grow = (long)gz * 1600 + (long)gy * 40;
    const unsigned sdst0 = (unsigned)__cvta_generic_to_shared(sh)
                         + (unsigned)(t * (SROW * 4) + 16);   // word 4, 16B aligned

    auto prefetch = [&](int ic, int buf) {
        if (!rowok) return;
        const float* src = xb + (size_t)ic * SP + grow;
        unsigned d = sdst0 + (unsigned)buf * (SLABVOL * 4);
        #pragma unroll
        for (int c = 0; c < 10; c++)
            asm volatile("cp.async.cg.shared.global [%0], [%1], 16;"
                         :: "r"(d + c * 16), "l"(src + c * 4));
    };

    // ---- compute setup ----
    const int ty = t / 5;                 // 0..39
    const int xs = (t % 5) * 8;           // 0,8,16,24,32
    const bool active = (t < 200);

    float acc[OCG][8];
    #pragma unroll
    for (int og = 0; og < OCG; og++)
        #pragma unroll
        for (int j = 0; j < 8; j++) acc[og][j] = 0.0f;

    __syncthreads();            // zero-fill visible before first prefetch
    prefetch(0, 0);
    asm volatile("cp.async.commit_group;");

    for (int ic = 0; ic < CIN; ic++) {
        __syncthreads();
        if (ic + 1 < CIN) prefetch(ic + 1, (ic + 1) & 1);
        asm volatile("cp.async.commit_group;");
        asm volatile("cp.async.wait_group 1;");
        __syncthreads();

        if (active) {
            const float* S = sh + (ic & 1) * SLABVOL;
            const float* W = wsh + ic * WICS;   // [ky][zz][kx][oc4]
            #pragma unroll 1
            for (int ky = 0; ky < 3; ky++) {
                #pragma unroll
                for (int zz = 0; zz < 3; zz++) {
                    const float* rowp = S + (zz * 42 + ty + ky) * SROW + 3 + xs;
                    float f[10];
                    f[0] = rowp[0];
                    float4 a = *(const float4*)(rowp + 1);
                    float4 c4 = *(const float4*)(rowp + 5);
                    f[1] = a.x; f[2] = a.y; f[3] = a.z; f[4] = a.w;
                    f[5] = c4.x; f[6] = c4.y; f[7] = c4.z; f[8] = c4.w;
                    f[9] = rowp[9];
                    #pragma unroll
                    for (int kx = 0; kx < 3; kx++) {
                        float4 w4 = *(const float4*)(W + ((ky * 3 + zz) * 3 + kx) * 4);
                        #pragma unroll
                        for (int j = 0; j < 8; j++) {
                            acc[0][j] = fmaf(w4.x, f[j + kx], acc[0][j]);
                            acc[1][j] = fmaf(w4.y, f[j + kx], acc[1][j]);
                            acc[2][j] = fmaf(w4.z, f[j + kx], acc[2][j]);
                            acc[3][j] = fmaf(w4.w, f[j + kx], acc[3][j]);
                        }
                    }
                }
            }
        }
    }

    // ---- epilogue: bias, store y, BN partial sums (per og) ----
    float s1[OCG], s2[OCG];
    #pragma unroll
    for (int og = 0; og < OCG; og++) { s1[og] = 0.0f; s2[og] = 0.0f; }

    if (active) {
        #pragma unroll
        for (int og = 0; og < OCG; og++) {
            const int oc = ocg * OCG + og;
            const float bias = g_bias[b * COUT + oc];
            float* yp = g_y + (size_t)(b * COUT + oc) * SP + z0 * 1600 + ty * 40 + xs;
            float4 q0, q1; float v;
            v = acc[og][0] + bias; s1[og] += v; s2[og] = fmaf(v, v, s2[og]); q0.x = v;
            v = acc[og][1] + bias; s1[og] += v; s2[og] = fmaf(v, v, s2[og]); q0.y = v;
            v = acc[og][2] + bias; s1[og] += v; s2[og] = fmaf(v, v, s2[og]); q0.z = v;
            v = acc[og][3] + bias; s1[og] += v; s2[og] = fmaf(v, v, s2[og]); q0.w = v;
            v = acc[og][4] + bias; s1[og] += v; s2[og] = fmaf(v, v, s2[og]); q1.x = v;
            v = acc[og][5] + bias; s1[og] += v; s2[og] = fmaf(v, v, s2[og]); q1.y = v;
            v = acc[og][6] + bias; s1[og] += v; s2[og] = fmaf(v, v, s2[og]); q1.z = v;
            v = acc[og][7] + bias; s1[og] += v; s2[og] = fmaf(v, v, s2[og]); q1.w = v;
            *(float4*)yp       = q0;
            *(float4*)(yp + 4) = q1;
        }
    }
    #pragma unroll
    for (int og = 0; og < OCG; og++) {
        #pragma unroll
        for (int o = 16; o > 0; o >>= 1) {
            s1[og] += __shfl_down_sync(0xffffffff, s1[og], o);
            s2[og] += __shfl_down_sync(0xffffffff, s2[og], o);
        }
    }
    const int wid = t >> 5, lane = t & 31;
    __syncthreads();
    if (lane == 0) {
        #pragma unroll
        for (int og = 0; og < OCG; og++) {
            red[og * 8 + wid]      = s1[og];
            red[32 + og * 8 + wid] = s2[og];
        }
    }
    __syncthreads();
    if (t < OCG) {
        float a = 0.0f, q = 0.0f;
        #pragma unroll
        for (int i = 0; i < 7; i++) { a += red[t * 8 + i]; q += red[32 + t * 8 + i]; }
        atomicAdd(&g_sum[ocg * OCG + t], a);
        atomicAdd(&g_sumsq[ocg * OCG + t], q);
    }
}

// ---------------------------------------------------------------------------
// Kernel 3: finalize BN -> per-channel scale/shift
// ---------------------------------------------------------------------------
__global__ void k_stats(const float* __restrict__ gamma,
                        const float* __restrict__ beta) {
    int c = threadIdx.x;
    if (c < COUT) {
        const float n = (float)(B_ * SP);
        float mean = g_sum[c] / n;
        float var  = g_sumsq[c] / n - mean * mean;
        float sc = gamma[c] * rsqrtf(var + 1e-5f);
        g_scale[c] = sc;
        g_shift[c] = beta[c] - mean * sc;
    }
}

// ---------------------------------------------------------------------------
// Kernel 4: affine + LeakyReLU + nearest upsample x2; float2 in, 4x float4 out
// ---------------------------------------------------------------------------
__global__ void __launch_bounds__(256)
k_up(float* __restrict__ out) {
    int idx = blockIdx.x * blockDim.x + threadIdx.x;  // over YTOT/2
    if (idx >= YTOT / 2) return;
    int i2 = idx * 2;
    int xw = i2 % 40;                 // even
    int rest = i2 / 40;
    int yw = rest % 40; rest /= 40;
    int zw = rest % 40; rest /= 40;
    int c  = rest % COUT;
    int b  = rest / COUT;

    float2 v = *(const float2*)&g_y[i2];
    float sc = g_scale[c], sf = g_shift[c];
    float a0 = fmaf(sc, v.x, sf); a0 = (a0 >= 0.0f) ? a0 : 0.1f * a0;
    float a1 = fmaf(sc, v.y, sf); a1 = (a1 >= 0.0f) ? a1 : 0.1f * a1;
    float4 p = make_float4(a0, a0, a1, a1);

    size_t base = ((size_t)(b * COUT + c) * 512000u)
                + (size_t)(2 * zw) * 6400u + (size_t)(2 * yw) * 80u + (size_t)(2 * xw);
    float4* o4 = (float4*)(out + base);
    o4[0]    = p;    // (2z,   2y  )
    o4[20]   = p;    // (2z,   2y+1)
    o4[1600] = p;    // (2z+1, 2y  )
    o4[1620] = p;    // (2z+1, 2y+1)
}

// ---------------------------------------------------------------------------
extern "C" void kernel_launch(void* const* d_in, const int* in_sizes, int n_in,
                              void* d_out, int out_size) {
    const float* x     = (const float*)d_in[0];
    const float* emb   = (const float*)d_in[1];
    const float* rw    = (const float*)d_in[2];
    const float* rb    = (const float*)d_in[3];
    const float* ek    = (const float*)d_in[4];
    const float* eb    = (const float*)d_in[5];
    const float* gamma = (const float*)d_in[6];
    const float* beta  = (const float*)d_in[7];
    float* out = (float*)d_out;

    k_route<<<(B_ * NOCG * WBLK + 255) / 256, 256>>>(emb, rw, rb, ek, eb);

    size_t shbytes = (size_t)(2 * SLABVOL + WBLK + 64) * sizeof(float);  // ~62.5 KB
    cudaFuncSetAttribute(k_conv, cudaFuncAttributeMaxDynamicSharedMemorySize, (int)shbytes);
    dim3 gconv(D_, NOCG, B_);
    k_conv<<<gconv, 224, shbytes>>>(x);

    k_stats<<<1, 32>>>(gamma, beta);

    k_up<<<(YTOT / 2 + 255) / 256, 256>>>(out);
}